// round 3
// baseline (speedup 1.0000x reference)
#include <cuda_runtime.h>
#include <cstddef>

// Problem constants (from reference: B=16, T=2048, D=256, WINDOW=128)
#define BB 16
#define TT 2048
#define DD 256
#define WIN 128
#define BT (BB*TT)          // 32768
#define QKV_LD 768          // q|k|v packed per row

// ---------------- scratch (static __device__ globals; no allocation) --------
__device__ float g_qkv[(size_t)BT * QKV_LD];     // [BT][768]: q|k|v, later sq|ek|u, later y|ek|u
__device__ float g_cw[(size_t)TT * 256];         // exp(w_bias)-1 on the band, 0 padded
__device__ float g_Spart[(size_t)BB * 16 * 512]; // partial sums per (b, t-chunk): [ek(256)|u(256)]
__device__ float g_S[(size_t)BB * 512];          // final per-(b,d) sums: [ek(256)|u(256)]

// ---------------- K: generic 128x128x8 SGEMM, 256 thr, 8x8 microtile -------
__global__ void __launch_bounds__(256) sgemm128(
    const float* __restrict__ A, int lda,
    const float* __restrict__ B, int ldb,
    float* __restrict__ C, int ldc, int K)
{
    __shared__ float As[8][128];
    __shared__ float Bs[8][128];
    const int tid = threadIdx.x;
    const int m0 = blockIdx.y * 128;
    const int n0 = blockIdx.x * 128;

    const int arow = tid >> 1;          // 0..127
    const int acol = (tid & 1) * 4;     // 0 or 4
    const int brow = tid >> 5;          // 0..7
    const int bcol = (tid & 31) * 4;    // 0..124

    const int tx = tid & 15;
    const int ty = tid >> 4;

    float acc[8][8];
#pragma unroll
    for (int i = 0; i < 8; i++)
#pragma unroll
        for (int j = 0; j < 8; j++) acc[i][j] = 0.f;

    const float* Aptr = A + (size_t)(m0 + arow) * lda + acol;
    const float* Bptr = B + (size_t)brow * ldb + n0 + bcol;

    for (int k0 = 0; k0 < K; k0 += 8) {
        float4 av = *(const float4*)(Aptr + k0);
        float4 bv = *(const float4*)(Bptr + (size_t)k0 * ldb);
        As[acol + 0][arow] = av.x;
        As[acol + 1][arow] = av.y;
        As[acol + 2][arow] = av.z;
        As[acol + 3][arow] = av.w;
        *(float4*)&Bs[brow][bcol] = bv;
        __syncthreads();
#pragma unroll
        for (int kk = 0; kk < 8; kk++) {
            float a0[8], b0[8];
            *(float4*)&a0[0] = *(const float4*)&As[kk][ty * 4];
            *(float4*)&a0[4] = *(const float4*)&As[kk][ty * 4 + 64];
            *(float4*)&b0[0] = *(const float4*)&Bs[kk][tx * 4];
            *(float4*)&b0[4] = *(const float4*)&Bs[kk][tx * 4 + 64];
#pragma unroll
            for (int i = 0; i < 8; i++)
#pragma unroll
                for (int j = 0; j < 8; j++) acc[i][j] += a0[i] * b0[j];
        }
        __syncthreads();
    }
#pragma unroll
    for (int i = 0; i < 8; i++) {
        int r = m0 + ty * 4 + ((i < 4) ? i : (64 + i - 4));
        float* crow = C + (size_t)r * ldc + n0;
        *(float4*)&crow[tx * 4]      = make_float4(acc[i][0], acc[i][1], acc[i][2], acc[i][3]);
        *(float4*)&crow[tx * 4 + 64] = make_float4(acc[i][4], acc[i][5], acc[i][6], acc[i][7]);
    }
}

// ---------------- K0: band coefficients cw[t][j] = exp(w_bias[t][t-127+j])-1
__global__ void build_cw(const float* __restrict__ wb)
{
    int t = blockIdx.x;
    int j = threadIdx.x;                 // 0..255
    int s = t - (WIN - 1) + j;           // t-127+j
    float v = 0.f;
    if (j < 2 * WIN - 1 && s >= 0 && s < TT)
        v = expf(wb[(size_t)t * TT + s]) - 1.f;
    g_cw[(size_t)t * 256 + j] = v;
}

// ---------------- K2: elementwise (sigmoid/exp/u) + partial T-sums ----------
__global__ void ew_reduce()
{
    int b = blockIdx.y;   // 0..15
    int c = blockIdx.x;   // 0..15 (chunk of 128 t's)
    int d = threadIdx.x;  // 0..255
    float se = 0.f, su = 0.f;
    for (int i = 0; i < 128; i++) {
        int t = c * 128 + i;
        size_t base = (size_t)(b * TT + t) * QKV_LD;
        float q = g_qkv[base + d];
        float k = g_qkv[base + 256 + d];
        float v = g_qkv[base + 512 + d];
        float ek = expf(k);
        float u  = ek * v;
        g_qkv[base + d]       = 1.f / (1.f + expf(-q));  // sigmoid(q)
        g_qkv[base + 256 + d] = ek;
        g_qkv[base + 512 + d] = u;
        se += ek;
        su += u;
    }
    size_t sb = ((size_t)b * 16 + c) * 512;
    g_Spart[sb + d]       = se;
    g_Spart[sb + 256 + d] = su;
}

// ---------------- K3: reduce partials over chunks ---------------------------
__global__ void reduce_final()
{
    int b = blockIdx.x;
    int i = threadIdx.x;  // 0..511
    float acc = 0.f;
    for (int c = 0; c < 16; c++)
        acc += g_Spart[((size_t)b * 16 + c) * 512 + i];
    g_S[(size_t)b * 512 + i] = acc;
}

// ---------------- K4: banded num/den + y = sigmoid(q)*num/den ---------------
// Block: (t-tile of 32, one batch). 256 threads, thread = d.
__global__ void __launch_bounds__(256) aft_band()
{
    __shared__ float su[16][256];
    __shared__ float sek[16][256];
    __shared__ float scw[32][16];

    const int b  = blockIdx.y;
    const int t0 = blockIdx.x * 32;
    const int d  = threadIdx.x;

    float accn[32], accd[32];
#pragma unroll
    for (int i = 0; i < 32; i++) { accn[i] = 0.f; accd[i] = 0.f; }

    const int sBase = t0 - (WIN - 1);   // t0-127
    // s range: [t0-127, t0+31+127] -> 286 values -> 18 chunks of 16
    for (int c = 0; c < 18; c++) {
        int s0 = sBase + c * 16;
        __syncthreads();   // previous compute done before overwriting smem
#pragma unroll
        for (int i = 0; i < 16; i++) {
            int s = s0 + i;
            bool valid = (s >= 0) && (s < TT);
            size_t base = (size_t)(b * TT + (valid ? s : 0)) * QKV_LD;
            su[i][d]  = valid ? g_qkv[base + 512 + d] : 0.f;
            sek[i][d] = valid ? g_qkv[base + 256 + d] : 0.f;
        }
        {
            int idx = d;
#pragma unroll
            for (int rep = 0; rep < 2; rep++, idx += 256) {
                int ti = idx >> 4, si = idx & 15;
                int j = (s0 + si) - (t0 + ti) + (WIN - 1);
                scw[ti][si] = ((unsigned)j < 255u) ? g_cw[(size_t)(t0 + ti) * 256 + j] : 0.f;
            }
        }
        __syncthreads();
        for (int si = 0; si < 16; si++) {
            float uu = su[si][d];
            float ee = sek[si][d];
#pragma unroll
            for (int ti = 0; ti < 32; ti++) {
                float w = scw[ti][si];
                accn[ti] += w * uu;
                accd[ti] += w * ee;
            }
        }
    }

    float sek_tot = g_S[(size_t)b * 512 + d];
    float su_tot  = g_S[(size_t)b * 512 + 256 + d];
#pragma unroll
    for (int ti = 0; ti < 32; ti++) {
        int t = t0 + ti;
        size_t base = (size_t)(b * TT + t) * QKV_LD;
        float sq  = g_qkv[base + d];
        float num = su_tot  + accn[ti];
        float den = sek_tot + accd[ti];
        g_qkv[base + d] = sq * num / den;   // y overwrites sigmoid(q) slot
    }
}

// ---------------- launch ----------------------------------------------------
extern "C" void kernel_launch(void* const* d_in, const int* in_sizes, int n_in,
                              void* d_out, int out_size)
{
    const float* x      = (const float*)d_in[0];
    const float* Wq     = (const float*)d_in[1];
    const float* Wk     = (const float*)d_in[2];
    const float* Wv     = (const float*)d_in[3];
    const float* Wo     = (const float*)d_in[4];
    const float* w_bias = (const float*)d_in[5];
    float* out = (float*)d_out;

    float* qkv = nullptr;
    cudaGetSymbolAddress((void**)&qkv, g_qkv);

    // q|k|v projections: three [32768,256]x[256,256] GEMMs into packed qkv
    dim3 gProj(DD / 128, BT / 128);   // (2, 256)
    sgemm128<<<gProj, 256>>>(x, DD, Wq, DD, qkv + 0,   QKV_LD, DD);
    sgemm128<<<gProj, 256>>>(x, DD, Wk, DD, qkv + 256, QKV_LD, DD);
    sgemm128<<<gProj, 256>>>(x, DD, Wv, DD, qkv + 512, QKV_LD, DD);

    // band coefficients (exp(w_bias)-1 on band, else 0)
    build_cw<<<TT, 256>>>(w_bias);

    // elementwise transform + global per-(b,d) sums
    ew_reduce<<<dim3(16, BB), 256>>>();
    reduce_final<<<BB, 512>>>();

    // banded numerator/denominator + gating
    aft_band<<<dim3(TT / 32, BB), 256>>>();

    // output projection: y @ Wo -> out
    sgemm128<<<gProj, 256>>>(qkv, QKV_LD, Wo, DD, out, DD, DD);
}

// round 5
// speedup vs baseline: 1.2428x; 1.2428x over previous
#include <cuda_runtime.h>
#include <cuda_bf16.h>
#include <cstddef>
#include <cstdint>

// Problem constants (B=16, T=2048, D=256, WINDOW=128)
#define BB 16
#define TT 2048
#define DD 256
#define WIN 128
#define BT (BB*TT)          // 32768
#define QKV_LD 768

// ---------------- scratch (__device__ globals; no allocation) ---------------
__device__ float g_qkv[(size_t)BT * QKV_LD];     // q|k|v -> sq|ek|u -> y|ek|u
__device__ float g_cw[(size_t)TT * 256];         // exp(w_bias)-1 on band, 0 pad
__device__ float g_Spart[(size_t)BB * 16 * 512];
__device__ float g_S[(size_t)BB * 512];

__device__ __nv_bfloat16 g_xh[(size_t)BT * 256];
__device__ __nv_bfloat16 g_xl[(size_t)BT * 256];
__device__ __nv_bfloat16 g_yh[(size_t)BT * 256];
__device__ __nv_bfloat16 g_yl[(size_t)BT * 256];
__device__ __nv_bfloat16 g_wqkvTh[(size_t)768 * 256];  // [N][K] = W^T fused q|k|v
__device__ __nv_bfloat16 g_wqkvTl[(size_t)768 * 256];
__device__ __nv_bfloat16 g_woTh[(size_t)256 * 256];
__device__ __nv_bfloat16 g_woTl[(size_t)256 * 256];

// ---------------- split helpers --------------------------------------------
__device__ __forceinline__ void split1(float v, __nv_bfloat16& h, __nv_bfloat16& l) {
    h = __float2bfloat16(v);
    l = __float2bfloat16(v - __bfloat162float(h));
}

// x (contiguous [BT][256]) -> bf16 hi/lo
__global__ void split_x(const float* __restrict__ src)
{
    size_t i = ((size_t)blockIdx.x * 256 + threadIdx.x) * 4;
    float4 v = *(const float4*)(src + i);
    __nv_bfloat16 h0, l0, h1, l1, h2, l2, h3, l3;
    split1(v.x, h0, l0); split1(v.y, h1, l1);
    split1(v.z, h2, l2); split1(v.w, h3, l3);
    g_xh[i] = h0; g_xh[i+1] = h1; g_xh[i+2] = h2; g_xh[i+3] = h3;
    g_xl[i] = l0; g_xl[i+1] = l1; g_xl[i+2] = l2; g_xl[i+3] = l3;
}

// y = g_qkv[:,0:256] (stride 768) -> bf16 hi/lo [BT][256]
__global__ void split_y()
{
    int r = blockIdx.x, d = threadIdx.x;
    float v = g_qkv[(size_t)r * QKV_LD + d];
    __nv_bfloat16 h, l; split1(v, h, l);
    g_yh[(size_t)r * 256 + d] = h;
    g_yl[(size_t)r * 256 + d] = l;
}

// weights: transpose + split. n in [0,768): fused Wq|Wk|Wv; n in [768,1024): Wo
__global__ void split_wT(const float* __restrict__ Wq, const float* __restrict__ Wk,
                         const float* __restrict__ Wv, const float* __restrict__ Wo)
{
    int n = blockIdx.x, k = threadIdx.x;
    if (n < 768) {
        const float* W = (n < 256) ? Wq : ((n < 512) ? Wk : Wv);
        float v = W[(size_t)k * 256 + (n & 255)];
        __nv_bfloat16 h, l; split1(v, h, l);
        g_wqkvTh[(size_t)n * 256 + k] = h;
        g_wqkvTl[(size_t)n * 256 + k] = l;
    } else {
        int nn = n - 768;
        float v = Wo[(size_t)k * 256 + nn];
        __nv_bfloat16 h, l; split1(v, h, l);
        g_woTh[(size_t)nn * 256 + k] = h;
        g_woTl[(size_t)nn * 256 + k] = l;
    }
}

// ---------------- bf16-split tensor-core GEMM -------------------------------
// C[M x N] = A[M x 256] * B^T, with B given as BT[N][256] (pre-transposed).
// Split: C += Ah*Bh + Ah*Bl + Al*Bh. Block 128x128x32, 8 warps (warp 64x32).
#define MMA_BF16(d, a, b) \
    asm volatile("mma.sync.aligned.m16n8k16.row.col.f32.bf16.bf16.f32 " \
                 "{%0,%1,%2,%3},{%4,%5,%6,%7},{%8,%9},{%0,%1,%2,%3};" \
                 : "+f"(d[0]), "+f"(d[1]), "+f"(d[2]), "+f"(d[3]) \
                 : "r"(a[0]), "r"(a[1]), "r"(a[2]), "r"(a[3]), "r"(b[0]), "r"(b[1]))

#define SPAD 40   // 32 + 8 pad (conflict-free fragment reads)

__global__ void __launch_bounds__(256, 2) gemm_bf16x3(
    const __nv_bfloat16* __restrict__ Ah, const __nv_bfloat16* __restrict__ Al,
    const __nv_bfloat16* __restrict__ BTh, const __nv_bfloat16* __restrict__ BTl,
    float* __restrict__ C, int ldc)
{
    __shared__ __nv_bfloat16 sAh[128 * SPAD], sAl[128 * SPAD];
    __shared__ __nv_bfloat16 sBh[128 * SPAD], sBl[128 * SPAD];

    const int K = 256;
    const int tid = threadIdx.x;
    const int m0 = blockIdx.y * 128, n0 = blockIdx.x * 128;

    const int lrow = tid >> 1;
    const int seg  = (tid & 1) * 16;                // bf16 elems
    const size_t aoff = (size_t)(m0 + lrow) * K + seg;
    const size_t boff = (size_t)(n0 + lrow) * K + seg;
    const int sidx = lrow * SPAD + seg;

    const int lane = tid & 31, w = tid >> 5;
    const int wm = w & 1, wn = w >> 1;
    const int quad = lane >> 2, qt = lane & 3;

    float acc[4][4][4];
#pragma unroll
    for (int i = 0; i < 4; i++)
#pragma unroll
        for (int j = 0; j < 4; j++)
#pragma unroll
            for (int e = 0; e < 4; e++) acc[i][j][e] = 0.f;

    for (int k0 = 0; k0 < K; k0 += 32) {
        const uint4* ga = (const uint4*)(Ah + aoff + k0);
        const uint4* gal = (const uint4*)(Al + aoff + k0);
        const uint4* gb = (const uint4*)(BTh + boff + k0);
        const uint4* gbl = (const uint4*)(BTl + boff + k0);
        *(uint4*)&sAh[sidx]     = ga[0];
        *(uint4*)&sAh[sidx + 8] = ga[1];
        *(uint4*)&sAl[sidx]     = gal[0];
        *(uint4*)&sAl[sidx + 8] = gal[1];
        *(uint4*)&sBh[sidx]     = gb[0];
        *(uint4*)&sBh[sidx + 8] = gb[1];
        *(uint4*)&sBl[sidx]     = gbl[0];
        *(uint4*)&sBl[sidx + 8] = gbl[1];
        __syncthreads();

#pragma unroll
        for (int kk = 0; kk < 32; kk += 16) {
            uint32_t afr[4][4], bh[4][2], bl[4][2];
            const int c = kk + qt * 2;
            // A_hi fragments
#pragma unroll
            for (int i = 0; i < 4; i++) {
                int r = wm * 64 + i * 16 + quad;
                afr[i][0] = *(const uint32_t*)&sAh[r * SPAD + c];
                afr[i][1] = *(const uint32_t*)&sAh[(r + 8) * SPAD + c];
                afr[i][2] = *(const uint32_t*)&sAh[r * SPAD + c + 8];
                afr[i][3] = *(const uint32_t*)&sAh[(r + 8) * SPAD + c + 8];
            }
            // B_hi fragments
#pragma unroll
            for (int j = 0; j < 4; j++) {
                int n = wn * 32 + j * 8 + quad;
                bh[j][0] = *(const uint32_t*)&sBh[n * SPAD + c];
                bh[j][1] = *(const uint32_t*)&sBh[n * SPAD + c + 8];
            }
            // Ah * Bh
#pragma unroll
            for (int i = 0; i < 4; i++)
#pragma unroll
                for (int j = 0; j < 4; j++) MMA_BF16(acc[i][j], afr[i], bh[j]);
            // B_lo fragments; Ah * Bl
#pragma unroll
            for (int j = 0; j < 4; j++) {
                int n = wn * 32 + j * 8 + quad;
                bl[j][0] = *(const uint32_t*)&sBl[n * SPAD + c];
                bl[j][1] = *(const uint32_t*)&sBl[n * SPAD + c + 8];
            }
#pragma unroll
            for (int i = 0; i < 4; i++)
#pragma unroll
                for (int j = 0; j < 4; j++) MMA_BF16(acc[i][j], afr[i], bl[j]);
            // A_lo fragments (overwrite afr); Al * Bh
#pragma unroll
            for (int i = 0; i < 4; i++) {
                int r = wm * 64 + i * 16 + quad;
                afr[i][0] = *(const uint32_t*)&sAl[r * SPAD + c];
                afr[i][1] = *(const uint32_t*)&sAl[(r + 8) * SPAD + c];
                afr[i][2] = *(const uint32_t*)&sAl[r * SPAD + c + 8];
                afr[i][3] = *(const uint32_t*)&sAl[(r + 8) * SPAD + c + 8];
            }
#pragma unroll
            for (int i = 0; i < 4; i++)
#pragma unroll
                for (int j = 0; j < 4; j++) MMA_BF16(acc[i][j], afr[i], bh[j]);
        }
        __syncthreads();
    }

#pragma unroll
    for (int i = 0; i < 4; i++) {
#pragma unroll
        for (int j = 0; j < 4; j++) {
            int r = m0 + wm * 64 + i * 16 + quad;
            int cc = n0 + wn * 32 + j * 8 + qt * 2;
            *(float2*)&C[(size_t)r * ldc + cc] = make_float2(acc[i][j][0], acc[i][j][1]);
            *(float2*)&C[(size_t)(r + 8) * ldc + cc] = make_float2(acc[i][j][2], acc[i][j][3]);
        }
    }
}

// ---------------- band coefficients ----------------------------------------
__global__ void build_cw(const float* __restrict__ wb)
{
    int t = blockIdx.x;
    int j = threadIdx.x;
    int s = t - (WIN - 1) + j;
    float v = 0.f;
    if (j < 2 * WIN - 1 && s >= 0 && s < TT)
        v = expf(wb[(size_t)t * TT + s]) - 1.f;
    g_cw[(size_t)t * 256 + j] = v;
}

// ---------------- elementwise + partial T-sums ------------------------------
__global__ void ew_reduce()
{
    int b = blockIdx.y;
    int c = blockIdx.x;
    int d = threadIdx.x;
    float se = 0.f, su = 0.f;
    for (int i = 0; i < 128; i++) {
        int t = c * 128 + i;
        size_t base = (size_t)(b * TT + t) * QKV_LD;
        float q = g_qkv[base + d];
        float k = g_qkv[base + 256 + d];
        float v = g_qkv[base + 512 + d];
        float ek = expf(k);
        float u  = ek * v;
        g_qkv[base + d]       = 1.f / (1.f + expf(-q));
        g_qkv[base + 256 + d] = ek;
        g_qkv[base + 512 + d] = u;
        se += ek;
        su += u;
    }
    size_t sb = ((size_t)b * 16 + c) * 512;
    g_Spart[sb + d]       = se;
    g_Spart[sb + 256 + d] = su;
}

__global__ void reduce_final()
{
    int b = blockIdx.x;
    int i = threadIdx.x;
    float acc = 0.f;
    for (int c = 0; c < 16; c++)
        acc += g_Spart[((size_t)b * 16 + c) * 512 + i];
    g_S[(size_t)b * 512 + i] = acc;
}

// ---------------- banded num/den + gating (fp32) ----------------------------
__global__ void __launch_bounds__(256) aft_band()
{
    __shared__ float su[16][256];
    __shared__ float sek[16][256];
    __shared__ float scw[32][16];

    const int b  = blockIdx.y;
    const int t0 = blockIdx.x * 32;
    const int d  = threadIdx.x;

    float accn[32], accd[32];
#pragma unroll
    for (int i = 0; i < 32; i++) { accn[i] = 0.f; accd[i] = 0.f; }

    const int sBase = t0 - (WIN - 1);
    for (int c = 0; c < 18; c++) {
        int s0 = sBase + c * 16;
        __syncthreads();
#pragma unroll
        for (int i = 0; i < 16; i++) {
            int s = s0 + i;
            bool valid = (s >= 0) && (s < TT);
            size_t base = (size_t)(b * TT + (valid ? s : 0)) * QKV_LD;
            su[i][d]  = valid ? g_qkv[base + 512 + d] : 0.f;
            sek[i][d] = valid ? g_qkv[base + 256 + d] : 0.f;
        }
        {
            int idx = d;
#pragma unroll
            for (int rep = 0; rep < 2; rep++, idx += 256) {
                int ti = idx >> 4, si = idx & 15;
                int j = (s0 + si) - (t0 + ti) + (WIN - 1);
                scw[ti][si] = ((unsigned)j < 255u) ? g_cw[(size_t)(t0 + ti) * 256 + j] : 0.f;
            }
        }
        __syncthreads();
        for (int si = 0; si < 16; si++) {
            float uu = su[si][d];
            float ee = sek[si][d];
#pragma unroll
            for (int ti = 0; ti < 32; ti++) {
                float wv = scw[ti][si];
                accn[ti] += wv * uu;
                accd[ti] += wv * ee;
            }
        }
    }

    float sek_tot = g_S[(size_t)b * 512 + d];
    float su_tot  = g_S[(size_t)b * 512 + 256 + d];
#pragma unroll
    for (int ti = 0; ti < 32; ti++) {
        int t = t0 + ti;
        size_t base = (size_t)(b * TT + t) * QKV_LD;
        float sq  = g_qkv[base + d];
        float num = su_tot  + accn[ti];
        float den = sek_tot + accd[ti];
        g_qkv[base + d] = sq * num / den;
    }
}

// ---------------- launch ----------------------------------------------------
extern "C" void kernel_launch(void* const* d_in, const int* in_sizes, int n_in,
                              void* d_out, int out_size)
{
    const float* x      = (const float*)d_in[0];
    const float* Wq     = (const float*)d_in[1];
    const float* Wk     = (const float*)d_in[2];
    const float* Wv     = (const float*)d_in[3];
    const float* Wo     = (const float*)d_in[4];
    const float* w_bias = (const float*)d_in[5];
    float* out = (float*)d_out;

    float* qkv = nullptr;
    cudaGetSymbolAddress((void**)&qkv, g_qkv);
    __nv_bfloat16 *xh, *xl, *yh, *yl, *wqh, *wql, *woh, *wol;
    cudaGetSymbolAddress((void**)&xh, g_xh);
    cudaGetSymbolAddress((void**)&xl, g_xl);
    cudaGetSymbolAddress((void**)&yh, g_yh);
    cudaGetSymbolAddress((void**)&yl, g_yl);
    cudaGetSymbolAddress((void**)&wqh, g_wqkvTh);
    cudaGetSymbolAddress((void**)&wql, g_wqkvTl);
    cudaGetSymbolAddress((void**)&woh, g_woTh);
    cudaGetSymbolAddress((void**)&wol, g_woTl);

    // split inputs to bf16 hi/lo (weights transposed+fused)
    split_x<<<(BT * 256) / (256 * 4), 256>>>(x);
    split_wT<<<1024, 256>>>(Wq, Wk, Wv, Wo);

    // fused QKV projection: [32768,256] x [256,768] -> packed q|k|v
    gemm_bf16x3<<<dim3(768 / 128, BT / 128), 256>>>(xh, xl, wqh, wql, qkv, QKV_LD);

    // band coefficients
    build_cw<<<TT, 256>>>(w_bias);

    // elementwise + global sums
    ew_reduce<<<dim3(16, BB), 256>>>();
    reduce_final<<<BB, 512>>>();

    // banded num/den + gating
    aft_band<<<dim3(TT / 32, BB), 256>>>();

    // y split + output projection
    split_y<<<BT, 256>>>();
    gemm_bf16x3<<<dim3(256 / 128, BT / 128), 256>>>(yh, yl, woh, wol, out, DD);
}

// round 6
// speedup vs baseline: 1.8077x; 1.4546x over previous
#include <cuda_runtime.h>
#include <cuda_bf16.h>
#include <cstddef>
#include <cstdint>

// Problem constants (B=16, T=2048, D=256, WINDOW=128)
#define BB 16
#define TT 2048
#define DD 256
#define WIN 128
#define BT (BB*TT)          // 32768
#define QKV_LD 768
#define PADT 2432           // 2048 + 2*192 pad rows (we use 128 front pad, 256 back)
#define KBAND 384

// ---------------- scratch (__device__ globals; no allocation) ---------------
__device__ float g_qkv[(size_t)BT * QKV_LD];     // q|k|v -> sq|..|..
__device__ float g_cwA[(size_t)TT * KBAND];      // per-t band coeffs, tf32-rounded
__device__ float g_uek[(size_t)BB * PADT * 512]; // padded [b][s+128][u(256)|ek(256)]
__device__ float g_nd[(size_t)BT * 512];         // band GEMM out: num|den corrections
__device__ float g_Spart[(size_t)BB * 16 * 512];
__device__ float g_S[(size_t)BB * 512];

__device__ __nv_bfloat16 g_xh[(size_t)BT * 256];
__device__ __nv_bfloat16 g_xl[(size_t)BT * 256];
__device__ __nv_bfloat16 g_yh[(size_t)BT * 256];
__device__ __nv_bfloat16 g_yl[(size_t)BT * 256];
__device__ __nv_bfloat16 g_wqkvTh[(size_t)768 * 256];
__device__ __nv_bfloat16 g_wqkvTl[(size_t)768 * 256];
__device__ __nv_bfloat16 g_woTh[(size_t)256 * 256];
__device__ __nv_bfloat16 g_woTl[(size_t)256 * 256];

// ---------------- helpers ---------------------------------------------------
__device__ __forceinline__ void split1(float v, __nv_bfloat16& h, __nv_bfloat16& l) {
    h = __float2bfloat16(v);
    l = __float2bfloat16(v - __bfloat162float(h));
}
__device__ __forceinline__ float to_tf32(float v) {
    float r;
    asm("cvt.rna.tf32.f32 %0, %1;" : "=f"(r) : "f"(v));
    return r;
}

// ---------------- input splits ----------------------------------------------
__global__ void split_x(const float* __restrict__ src)
{
    size_t i = ((size_t)blockIdx.x * 256 + threadIdx.x) * 4;
    float4 v = *(const float4*)(src + i);
    __nv_bfloat16 h0, l0, h1, l1, h2, l2, h3, l3;
    split1(v.x, h0, l0); split1(v.y, h1, l1);
    split1(v.z, h2, l2); split1(v.w, h3, l3);
    g_xh[i] = h0; g_xh[i+1] = h1; g_xh[i+2] = h2; g_xh[i+3] = h3;
    g_xl[i] = l0; g_xl[i+1] = l1; g_xl[i+2] = l2; g_xl[i+3] = l3;
}

__global__ void split_wT(const float* __restrict__ Wq, const float* __restrict__ Wk,
                         const float* __restrict__ Wv, const float* __restrict__ Wo)
{
    int n = blockIdx.x, k = threadIdx.x;
    if (n < 768) {
        const float* W = (n < 256) ? Wq : ((n < 512) ? Wk : Wv);
        float v = W[(size_t)k * 256 + (n & 255)];
        __nv_bfloat16 h, l; split1(v, h, l);
        g_wqkvTh[(size_t)n * 256 + k] = h;
        g_wqkvTl[(size_t)n * 256 + k] = l;
    } else {
        int nn = n - 768;
        float v = Wo[(size_t)k * 256 + nn];
        __nv_bfloat16 h, l; split1(v, h, l);
        g_woTh[(size_t)nn * 256 + k] = h;
        g_woTl[(size_t)nn * 256 + k] = l;
    }
}

// ---------------- bf16-split tensor-core GEMM (projections) -----------------
#define MMA_BF16(d, a, b) \
    asm volatile("mma.sync.aligned.m16n8k16.row.col.f32.bf16.bf16.f32 " \
                 "{%0,%1,%2,%3},{%4,%5,%6,%7},{%8,%9},{%0,%1,%2,%3};" \
                 : "+f"(d[0]), "+f"(d[1]), "+f"(d[2]), "+f"(d[3]) \
                 : "r"(a[0]), "r"(a[1]), "r"(a[2]), "r"(a[3]), "r"(b[0]), "r"(b[1]))

#define SPAD 40

__global__ void __launch_bounds__(256, 2) gemm_bf16x3(
    const __nv_bfloat16* __restrict__ Ah, const __nv_bfloat16* __restrict__ Al,
    const __nv_bfloat16* __restrict__ BTh, const __nv_bfloat16* __restrict__ BTl,
    float* __restrict__ C, int ldc)
{
    __shared__ __nv_bfloat16 sAh[128 * SPAD], sAl[128 * SPAD];
    __shared__ __nv_bfloat16 sBh[128 * SPAD], sBl[128 * SPAD];

    const int K = 256;
    const int tid = threadIdx.x;
    const int m0 = blockIdx.y * 128, n0 = blockIdx.x * 128;

    const int lrow = tid >> 1;
    const int seg  = (tid & 1) * 16;
    const size_t aoff = (size_t)(m0 + lrow) * K + seg;
    const size_t boff = (size_t)(n0 + lrow) * K + seg;
    const int sidx = lrow * SPAD + seg;

    const int lane = tid & 31, w = tid >> 5;
    const int wm = w & 1, wn = w >> 1;
    const int quad = lane >> 2, qt = lane & 3;

    float acc[4][4][4];
#pragma unroll
    for (int i = 0; i < 4; i++)
#pragma unroll
        for (int j = 0; j < 4; j++)
#pragma unroll
            for (int e = 0; e < 4; e++) acc[i][j][e] = 0.f;

    for (int k0 = 0; k0 < K; k0 += 32) {
        const uint4* ga = (const uint4*)(Ah + aoff + k0);
        const uint4* gal = (const uint4*)(Al + aoff + k0);
        const uint4* gb = (const uint4*)(BTh + boff + k0);
        const uint4* gbl = (const uint4*)(BTl + boff + k0);
        *(uint4*)&sAh[sidx]     = ga[0];
        *(uint4*)&sAh[sidx + 8] = ga[1];
        *(uint4*)&sAl[sidx]     = gal[0];
        *(uint4*)&sAl[sidx + 8] = gal[1];
        *(uint4*)&sBh[sidx]     = gb[0];
        *(uint4*)&sBh[sidx + 8] = gb[1];
        *(uint4*)&sBl[sidx]     = gbl[0];
        *(uint4*)&sBl[sidx + 8] = gbl[1];
        __syncthreads();

#pragma unroll
        for (int kk = 0; kk < 32; kk += 16) {
            uint32_t afr[4][4], bh[4][2], bl[4][2];
            const int c = kk + qt * 2;
#pragma unroll
            for (int i = 0; i < 4; i++) {
                int r = wm * 64 + i * 16 + quad;
                afr[i][0] = *(const uint32_t*)&sAh[r * SPAD + c];
                afr[i][1] = *(const uint32_t*)&sAh[(r + 8) * SPAD + c];
                afr[i][2] = *(const uint32_t*)&sAh[r * SPAD + c + 8];
                afr[i][3] = *(const uint32_t*)&sAh[(r + 8) * SPAD + c + 8];
            }
#pragma unroll
            for (int j = 0; j < 4; j++) {
                int n = wn * 32 + j * 8 + quad;
                bh[j][0] = *(const uint32_t*)&sBh[n * SPAD + c];
                bh[j][1] = *(const uint32_t*)&sBh[n * SPAD + c + 8];
            }
#pragma unroll
            for (int i = 0; i < 4; i++)
#pragma unroll
                for (int j = 0; j < 4; j++) MMA_BF16(acc[i][j], afr[i], bh[j]);
#pragma unroll
            for (int j = 0; j < 4; j++) {
                int n = wn * 32 + j * 8 + quad;
                bl[j][0] = *(const uint32_t*)&sBl[n * SPAD + c];
                bl[j][1] = *(const uint32_t*)&sBl[n * SPAD + c + 8];
            }
#pragma unroll
            for (int i = 0; i < 4; i++)
#pragma unroll
                for (int j = 0; j < 4; j++) MMA_BF16(acc[i][j], afr[i], bl[j]);
#pragma unroll
            for (int i = 0; i < 4; i++) {
                int r = wm * 64 + i * 16 + quad;
                afr[i][0] = *(const uint32_t*)&sAl[r * SPAD + c];
                afr[i][1] = *(const uint32_t*)&sAl[(r + 8) * SPAD + c];
                afr[i][2] = *(const uint32_t*)&sAl[r * SPAD + c + 8];
                afr[i][3] = *(const uint32_t*)&sAl[(r + 8) * SPAD + c + 8];
            }
#pragma unroll
            for (int i = 0; i < 4; i++)
#pragma unroll
                for (int j = 0; j < 4; j++) MMA_BF16(acc[i][j], afr[i], bh[j]);
        }
        __syncthreads();
    }

#pragma unroll
    for (int i = 0; i < 4; i++) {
#pragma unroll
        for (int j = 0; j < 4; j++) {
            int r = m0 + wm * 64 + i * 16 + quad;
            int cc = n0 + wn * 32 + j * 8 + qt * 2;
            *(float2*)&C[(size_t)r * ldc + cc] = make_float2(acc[i][j][0], acc[i][j][1]);
            *(float2*)&C[(size_t)(r + 8) * ldc + cc] = make_float2(acc[i][j][2], acc[i][j][3]);
        }
    }
}

// ---------------- band coefficient matrix A [2048][384] ---------------------
// cwA[t][j] corresponds to s = (t>>7)*128 - 127 + j.
__global__ void build_cwA(const float* __restrict__ wb)
{
    int t = blockIdx.x;
    int j = threadIdx.x;           // 0..383
    int t0 = (t >> 7) << 7;
    int s = t0 - (WIN - 1) + j;
    float v = 0.f;
    if (s >= 0 && s < TT) {
        int dlt = t - s;
        if (dlt < WIN && dlt > -WIN)
            v = to_tf32(expf(wb[(size_t)t * TT + s]) - 1.f);
    }
    g_cwA[(size_t)t * KBAND + j] = v;
}

// zero the pad rows of g_uek: rows [0,128) and [2176,2432) per b
__global__ void zero_uek_pad()
{
    size_t i = (size_t)blockIdx.x * 256 + threadIdx.x;  // over 16*384*512/4 float4s
    size_t e = i * 4;
    int b = e / (384 * 512);
    int rem = e % (384 * 512);
    int r = rem / 512;
    int c = rem % 512;
    int p = (r < 128) ? r : (r + 2048);
    *(float4*)&g_uek[((size_t)b * PADT + p) * 512 + c] = make_float4(0.f, 0.f, 0.f, 0.f);
}

// ---------------- elementwise + uek materialization + partial sums ----------
__global__ void ew_reduce()
{
    int b = blockIdx.y;
    int c = blockIdx.x;
    int d = threadIdx.x;
    float se = 0.f, su = 0.f;
    for (int i = 0; i < 128; i++) {
        int t = c * 128 + i;
        size_t base = (size_t)(b * TT + t) * QKV_LD;
        float q = g_qkv[base + d];
        float k = g_qkv[base + 256 + d];
        float v = g_qkv[base + 512 + d];
        float ek = expf(k);
        float u  = ek * v;
        g_qkv[base + d] = 1.f / (1.f + expf(-q));    // sigmoid(q)
        size_t up = ((size_t)b * PADT + t + 128) * 512;
        g_uek[up + d]       = to_tf32(u);            // num operand
        g_uek[up + 256 + d] = to_tf32(ek);           // den operand
        se += ek;
        su += u;
    }
    size_t sb = ((size_t)b * 16 + c) * 512;
    g_Spart[sb + d]       = se;
    g_Spart[sb + 256 + d] = su;
}

__global__ void reduce_final()
{
    int b = blockIdx.x;
    int i = threadIdx.x;
    float acc = 0.f;
    for (int c = 0; c < 16; c++)
        acc += g_Spart[((size_t)b * 16 + c) * 512 + i];
    g_S[(size_t)b * 512 + i] = acc;
}

// ---------------- band GEMM: tf32 mma, C[128x128] = A[128x384] * B[384x128] -
#define MMA_TF32(d, a, b) \
    asm volatile("mma.sync.aligned.m16n8k8.row.col.f32.tf32.tf32.f32 " \
                 "{%0,%1,%2,%3},{%4,%5,%6,%7},{%8,%9},{%0,%1,%2,%3};" \
                 : "+f"(d[0]), "+f"(d[1]), "+f"(d[2]), "+f"(d[3]) \
                 : "r"(a[0]), "r"(a[1]), "r"(a[2]), "r"(a[3]), "r"(b[0]), "r"(b[1]))

#define SPA 44    // sA row length (32 k + 12 pad): 12m+qt perm -> conflict-free
#define SPB 136   // sB row length (128 n + 8 pad): 8qt+n perm -> conflict-free

__global__ void __launch_bounds__(256, 2) band_gemm()
{
    __shared__ float sA[128 * SPA];   // [m][k]
    __shared__ float sB[32 * SPB];    // [k][n]

    const int tid = threadIdx.x;
    const int n0 = blockIdx.x * 128;        // 0..383 (cols of u|ek)
    const int t0 = blockIdx.y * 128;        // t tile
    const int b  = blockIdx.z;

    const float* Ag = g_cwA + (size_t)t0 * KBAND;
    const float* Bg = g_uek + (size_t)b * PADT * 512;

    // A loader: row tid>>1, 16-col segment (tid&1)*16
    const int alrow = tid >> 1;
    const int akseg = (tid & 1) * 16;
    // B loader: row tid>>3, 16-col segment (tid&7)*16
    const int bkrow = tid >> 3;
    const int bcseg = (tid & 7) * 16;

    const int lane = tid & 31, w = tid >> 5;
    const int wm = w & 1, wn = w >> 1;       // warp tile 64x32
    const int quad = lane >> 2, qt = lane & 3;

    float acc[4][4][4];
#pragma unroll
    for (int i = 0; i < 4; i++)
#pragma unroll
        for (int j = 0; j < 4; j++)
#pragma unroll
            for (int e = 0; e < 4; e++) acc[i][j][e] = 0.f;

    for (int k0 = 0; k0 < KBAND; k0 += 32) {
        const float* ap = Ag + (size_t)alrow * KBAND + k0 + akseg;
        const float* bp = Bg + (size_t)(t0 + 1 + k0 + bkrow) * 512 + n0 + bcseg;
        float* sa = &sA[alrow * SPA + akseg];
        float* sb = &sB[bkrow * SPB + bcseg];
#pragma unroll
        for (int cc = 0; cc < 4; cc++) *(float4*)(sa + cc * 4) = *(const float4*)(ap + cc * 4);
#pragma unroll
        for (int cc = 0; cc < 4; cc++) *(float4*)(sb + cc * 4) = *(const float4*)(bp + cc * 4);
        __syncthreads();

#pragma unroll
        for (int kk = 0; kk < 32; kk += 8) {
            uint32_t afr[4][4], bfr[4][2];
#pragma unroll
            for (int i = 0; i < 4; i++) {
                int m = wm * 64 + i * 16 + quad;
                afr[i][0] = *(const uint32_t*)&sA[m * SPA + kk + qt];
                afr[i][1] = *(const uint32_t*)&sA[(m + 8) * SPA + kk + qt];
                afr[i][2] = *(const uint32_t*)&sA[m * SPA + kk + qt + 4];
                afr[i][3] = *(const uint32_t*)&sA[(m + 8) * SPA + kk + qt + 4];
            }
#pragma unroll
            for (int j = 0; j < 4; j++) {
                int n = wn * 32 + j * 8 + quad;
                bfr[j][0] = *(const uint32_t*)&sB[(kk + qt) * SPB + n];
                bfr[j][1] = *(const uint32_t*)&sB[(kk + qt + 4) * SPB + n];
            }
#pragma unroll
            for (int i = 0; i < 4; i++)
#pragma unroll
                for (int j = 0; j < 4; j++) MMA_TF32(acc[i][j], afr[i], bfr[j]);
        }
        __syncthreads();
    }

    float* C = g_nd + (size_t)(b * TT + t0) * 512;
#pragma unroll
    for (int i = 0; i < 4; i++) {
#pragma unroll
        for (int j = 0; j < 4; j++) {
            int r = wm * 64 + i * 16 + quad;
            int cc = n0 + wn * 32 + j * 8 + qt * 2;
            *(float2*)&C[(size_t)r * 512 + cc] = make_float2(acc[i][j][0], acc[i][j][1]);
            *(float2*)&C[(size_t)(r + 8) * 512 + cc] = make_float2(acc[i][j][2], acc[i][j][3]);
        }
    }
}

// ---------------- final gating + split for output GEMM ----------------------
__global__ void ybuild()
{
    int r = blockIdx.x;            // 0..32767 (b*2048+t)
    int b = r >> 11;
    int d = threadIdx.x;
    float sq  = g_qkv[(size_t)r * QKV_LD + d];
    float num = g_S[(size_t)b * 512 + 256 + d] + g_nd[(size_t)r * 512 + d];
    float den = g_S[(size_t)b * 512 + d]       + g_nd[(size_t)r * 512 + 256 + d];
    float y = sq * num / den;
    __nv_bfloat16 h, l; split1(y, h, l);
    g_yh[(size_t)r * 256 + d] = h;
    g_yl[(size_t)r * 256 + d] = l;
}

// ---------------- launch ----------------------------------------------------
extern "C" void kernel_launch(void* const* d_in, const int* in_sizes, int n_in,
                              void* d_out, int out_size)
{
    const float* x      = (const float*)d_in[0];
    const float* Wq     = (const float*)d_in[1];
    const float* Wk     = (const float*)d_in[2];
    const float* Wv     = (const float*)d_in[3];
    const float* Wo     = (const float*)d_in[4];
    const float* w_bias = (const float*)d_in[5];
    float* out = (float*)d_out;

    float* qkv = nullptr;
    cudaGetSymbolAddress((void**)&qkv, g_qkv);
    __nv_bfloat16 *xh, *xl, *yh, *yl, *wqh, *wql, *woh, *wol;
    cudaGetSymbolAddress((void**)&xh, g_xh);
    cudaGetSymbolAddress((void**)&xl, g_xl);
    cudaGetSymbolAddress((void**)&yh, g_yh);
    cudaGetSymbolAddress((void**)&yl, g_yl);
    cudaGetSymbolAddress((void**)&wqh, g_wqkvTh);
    cudaGetSymbolAddress((void**)&wql, g_wqkvTl);
    cudaGetSymbolAddress((void**)&woh, g_woTh);
    cudaGetSymbolAddress((void**)&wol, g_woTl);

    // splits + band coefficient matrix + pad zeroing (independent prep)
    split_x<<<(BT * 256) / (256 * 4), 256>>>(x);
    split_wT<<<1024, 256>>>(Wq, Wk, Wv, Wo);
    build_cwA<<<TT, KBAND>>>(w_bias);
    zero_uek_pad<<<(BB * 384 * 512) / (256 * 4), 256>>>();

    // fused QKV projection: [32768,256] x [256,768] -> packed q|k|v
    gemm_bf16x3<<<dim3(768 / 128, BT / 128), 256>>>(xh, xl, wqh, wql, qkv, QKV_LD);

    // elementwise + uek materialization + global sums
    ew_reduce<<<dim3(16, BB), 256>>>();
    reduce_final<<<BB, 512>>>();

    // banded num/den corrections via tf32 tensor cores
    band_gemm<<<dim3(4, 16, BB), 256>>>();

    // gating + split, then output projection
    ybuild<<<BT, 256>>>();
    gemm_bf16x3<<<dim3(256 / 128, BT / 128), 256>>>(yh, yl, woh, wol, out, DD);
}

// round 8
// speedup vs baseline: 1.9918x; 1.1018x over previous
#include <cuda_runtime.h>
#include <cuda_bf16.h>
#include <cstddef>
#include <cstdint>

// Problem constants (B=16, T=2048, D=256, WINDOW=128)
#define BB 16
#define TT 2048
#define DD 256
#define WIN 128
#define BT (BB*TT)          // 32768
#define QKV_LD 768
#define PADT 2432
#define KBAND 384

// ---------------- scratch (__device__ globals; no allocation) ---------------
__device__ float g_qkv[(size_t)BT * QKV_LD];
__device__ float g_cwA[(size_t)TT * KBAND];
__device__ float g_uek[(size_t)BB * PADT * 512];
__device__ float g_nd[(size_t)BT * 512];
__device__ float g_Spart[(size_t)BB * 16 * 512];
__device__ float g_S[(size_t)BB * 512];

__device__ __nv_bfloat16 g_xh[(size_t)BT * 256];
__device__ __nv_bfloat16 g_xl[(size_t)BT * 256];
__device__ __nv_bfloat16 g_yh[(size_t)BT * 256];
__device__ __nv_bfloat16 g_yl[(size_t)BT * 256];
__device__ __nv_bfloat16 g_wqkvTh[(size_t)768 * 256];
__device__ __nv_bfloat16 g_wqkvTl[(size_t)768 * 256];
__device__ __nv_bfloat16 g_woTh[(size_t)256 * 256];
__device__ __nv_bfloat16 g_woTl[(size_t)256 * 256];

// ---------------- helpers ---------------------------------------------------
__device__ __forceinline__ void split1(float v, __nv_bfloat16& h, __nv_bfloat16& l) {
    h = __float2bfloat16(v);
    l = __float2bfloat16(v - __bfloat162float(h));
}
__device__ __forceinline__ float to_tf32(float v) {
    float r;
    asm("cvt.rna.tf32.f32 %0, %1;" : "=f"(r) : "f"(v));
    return r;
}
__device__ __forceinline__ uint32_t smem_u32(const void* p) {
    return (uint32_t)__cvta_generic_to_shared(p);
}

// ---------------- input splits ----------------------------------------------
__global__ void split_x(const float* __restrict__ src)
{
    size_t i = ((size_t)blockIdx.x * 256 + threadIdx.x) * 4;
    float4 v = *(const float4*)(src + i);
    __nv_bfloat16 h0, l0, h1, l1, h2, l2, h3, l3;
    split1(v.x, h0, l0); split1(v.y, h1, l1);
    split1(v.z, h2, l2); split1(v.w, h3, l3);
    g_xh[i] = h0; g_xh[i+1] = h1; g_xh[i+2] = h2; g_xh[i+3] = h3;
    g_xl[i] = l0; g_xl[i+1] = l1; g_xl[i+2] = l2; g_xl[i+3] = l3;
}

__global__ void split_wT(const float* __restrict__ Wq, const float* __restrict__ Wk,
                         const float* __restrict__ Wv, const float* __restrict__ Wo)
{
    int n = blockIdx.x, k = threadIdx.x;
    if (n < 768) {
        const float* W = (n < 256) ? Wq : ((n < 512) ? Wk : Wv);
        float v = W[(size_t)k * 256 + (n & 255)];
        __nv_bfloat16 h, l; split1(v, h, l);
        g_wqkvTh[(size_t)n * 256 + k] = h;
        g_wqkvTl[(size_t)n * 256 + k] = l;
    } else {
        int nn = n - 768;
        float v = Wo[(size_t)k * 256 + nn];
        __nv_bfloat16 h, l; split1(v, h, l);
        g_woTh[(size_t)nn * 256 + k] = h;
        g_woTl[(size_t)nn * 256 + k] = l;
    }
}

// ---------------- bf16-split tensor-core GEMM (cp.async + ldmatrix) ---------
#define MMA_BF16(d, a, b) \
    asm volatile("mma.sync.aligned.m16n8k16.row.col.f32.bf16.bf16.f32 " \
                 "{%0,%1,%2,%3},{%4,%5,%6,%7},{%8,%9},{%0,%1,%2,%3};" \
                 : "+f"(d[0]), "+f"(d[1]), "+f"(d[2]), "+f"(d[3]) \
                 : "r"(a[0]), "r"(a[1]), "r"(a[2]), "r"(a[3]), "r"(b[0]), "r"(b[1]))

#define LDSM_X4(r0, r1, r2, r3, addr) \
    asm volatile("ldmatrix.sync.aligned.m8n8.x4.shared.b16 {%0,%1,%2,%3}, [%4];" \
                 : "=r"(r0), "=r"(r1), "=r"(r2), "=r"(r3) : "r"(addr))

#define CP16(dst, src) \
    asm volatile("cp.async.cg.shared.global [%0], [%1], 16;" :: "r"(dst), "l"(src))

#define SPAD 40
#define TILE_E (128 * SPAD)          // bf16 elems per tile
#define GSMEM_BYTES (2 * 4 * TILE_E * 2)   // 2 stages x 4 tiles x bf16

__device__ __forceinline__ void gload(__nv_bfloat16* buf,
    const __nv_bfloat16* pAh, const __nv_bfloat16* pAl,
    const __nv_bfloat16* pBh, const __nv_bfloat16* pBl, int sidx)
{
    uint32_t d;
    d = smem_u32(buf + sidx);
    CP16(d, pAh); CP16(d + 16, pAh + 8);
    d = smem_u32(buf + TILE_E + sidx);
    CP16(d, pAl); CP16(d + 16, pAl + 8);
    d = smem_u32(buf + 2 * TILE_E + sidx);
    CP16(d, pBh); CP16(d + 16, pBh + 8);
    d = smem_u32(buf + 3 * TILE_E + sidx);
    CP16(d, pBl); CP16(d + 16, pBl + 8);
    asm volatile("cp.async.commit_group;");
}

__global__ void __launch_bounds__(256, 2) gemm_bf16x3(
    const __nv_bfloat16* __restrict__ Ah, const __nv_bfloat16* __restrict__ Al,
    const __nv_bfloat16* __restrict__ BTh, const __nv_bfloat16* __restrict__ BTl,
    float* __restrict__ C, int ldc)
{
    extern __shared__ __nv_bfloat16 smem[];
    const int K = 256;
    const int tid = threadIdx.x;
    const int m0 = blockIdx.y * 128, n0 = blockIdx.x * 128;

    const int lrow = tid >> 1;
    const int seg  = (tid & 1) * 16;
    const size_t aoff = (size_t)(m0 + lrow) * K + seg;
    const size_t boff = (size_t)(n0 + lrow) * K + seg;
    const int sidx = lrow * SPAD + seg;

    const int lane = tid & 31, w = tid >> 5;
    const int wm = w & 1, wn = w >> 1;

    // ldmatrix per-lane row/col bases
    const int ar = wm * 64 + (lane & 15);
    const int ac = (lane >> 4) << 3;                       // 0 or 8
    const int br = wn * 32 + (lane & 7) + ((lane >> 4) << 3);
    const int bc = ((lane >> 3) & 1) << 3;

    const int quad = lane >> 2, qt = lane & 3;

    float acc[4][4][4];
#pragma unroll
    for (int i = 0; i < 4; i++)
#pragma unroll
        for (int j = 0; j < 4; j++)
#pragma unroll
            for (int e = 0; e < 4; e++) acc[i][j][e] = 0.f;

    int stage = 0;
    gload(smem, Ah + aoff, Al + aoff, BTh + boff, BTl + boff, sidx);

    for (int step = 0; step < 8; step++) {
        if (step < 7) {
            int kn = (step + 1) * 32;
            gload(smem + (stage ^ 1) * 4 * TILE_E,
                  Ah + aoff + kn, Al + aoff + kn,
                  BTh + boff + kn, BTl + boff + kn, sidx);
            asm volatile("cp.async.wait_group 1;");
        } else {
            asm volatile("cp.async.wait_group 0;");
        }
        __syncthreads();

        __nv_bfloat16* buf = smem + stage * 4 * TILE_E;
        const uint32_t aBase = smem_u32(buf);
        const uint32_t bBase = smem_u32(buf + 2 * TILE_E);

#pragma unroll
        for (int kk = 0; kk < 32; kk += 16) {
            uint32_t afr[4][4], bh[4][2], bl[4][2];
            const uint32_t aAddr = aBase + (uint32_t)((ar * SPAD + kk + ac) * 2);
            const uint32_t bAddr = bBase + (uint32_t)((br * SPAD + kk + bc) * 2);

            // A_hi fragments (4 x ldmatrix.x4)
#pragma unroll
            for (int i = 0; i < 4; i++)
                LDSM_X4(afr[i][0], afr[i][1], afr[i][2], afr[i][3],
                        aAddr + (uint32_t)(i * 16 * SPAD * 2));
            // B_hi fragments (2 x ldmatrix.x4 -> 4 j's)
            LDSM_X4(bh[0][0], bh[0][1], bh[1][0], bh[1][1], bAddr);
            LDSM_X4(bh[2][0], bh[2][1], bh[3][0], bh[3][1],
                    bAddr + (uint32_t)(16 * SPAD * 2));
#pragma unroll
            for (int i = 0; i < 4; i++)
#pragma unroll
                for (int j = 0; j < 4; j++) MMA_BF16(acc[i][j], afr[i], bh[j]);

            // B_lo fragments
            LDSM_X4(bl[0][0], bl[0][1], bl[1][0], bl[1][1],
                    bAddr + (uint32_t)(TILE_E * 2));
            LDSM_X4(bl[2][0], bl[2][1], bl[3][0], bl[3][1],
                    bAddr + (uint32_t)(TILE_E * 2 + 16 * SPAD * 2));
#pragma unroll
            for (int i = 0; i < 4; i++)
#pragma unroll
                for (int j = 0; j < 4; j++) MMA_BF16(acc[i][j], afr[i], bl[j]);

            // A_lo fragments (overwrite afr)
#pragma unroll
            for (int i = 0; i < 4; i++)
                LDSM_X4(afr[i][0], afr[i][1], afr[i][2], afr[i][3],
                        aAddr + (uint32_t)(TILE_E * 2 + i * 16 * SPAD * 2));
#pragma unroll
            for (int i = 0; i < 4; i++)
#pragma unroll
                for (int j = 0; j < 4; j++) MMA_BF16(acc[i][j], afr[i], bh[j]);
        }
        __syncthreads();
        stage ^= 1;
    }

#pragma unroll
    for (int i = 0; i < 4; i++) {
#pragma unroll
        for (int j = 0; j < 4; j++) {
            int r = m0 + wm * 64 + i * 16 + quad;
            int cc = n0 + wn * 32 + j * 8 + qt * 2;
            *(float2*)&C[(size_t)r * ldc + cc] = make_float2(acc[i][j][0], acc[i][j][1]);
            *(float2*)&C[(size_t)(r + 8) * ldc + cc] = make_float2(acc[i][j][2], acc[i][j][3]);
        }
    }
}

// ---------------- band coefficient matrix A [2048][384] ---------------------
__global__ void build_cwA(const float* __restrict__ wb)
{
    int t = blockIdx.x;
    int j = threadIdx.x;
    int t0 = (t >> 7) << 7;
    int s = t0 - (WIN - 1) + j;
    float v = 0.f;
    if (s >= 0 && s < TT) {
        int dlt = t - s;
        if (dlt < WIN && dlt > -WIN)
            v = to_tf32(expf(wb[(size_t)t * TT + s]) - 1.f);
    }
    g_cwA[(size_t)t * KBAND + j] = v;
}

__global__ void zero_uek_pad()
{
    size_t i = (size_t)blockIdx.x * 256 + threadIdx.x;
    size_t e = i * 4;
    int b = e / (384 * 512);
    int rem = e % (384 * 512);
    int r = rem / 512;
    int c = rem % 512;
    int p = (r < 128) ? r : (r + 2048);
    *(float4*)&g_uek[((size_t)b * PADT + p) * 512 + c] = make_float4(0.f, 0.f, 0.f, 0.f);
}

// ---------------- elementwise + uek materialization + partial sums ----------
__global__ void ew_reduce()
{
    int b = blockIdx.y;
    int c = blockIdx.x;
    int d = threadIdx.x;
    float se = 0.f, su = 0.f;
    for (int i = 0; i < 128; i++) {
        int t = c * 128 + i;
        size_t base = (size_t)(b * TT + t) * QKV_LD;
        float q = g_qkv[base + d];
        float k = g_qkv[base + 256 + d];
        float v = g_qkv[base + 512 + d];
        float ek = expf(k);
        float u  = ek * v;
        g_qkv[base + d] = 1.f / (1.f + expf(-q));
        size_t up = ((size_t)b * PADT + t + 128) * 512;
        g_uek[up + d]       = to_tf32(u);
        g_uek[up + 256 + d] = to_tf32(ek);
        se += ek;
        su += u;
    }
    size_t sb = ((size_t)b * 16 + c) * 512;
    g_Spart[sb + d]       = se;
    g_Spart[sb + 256 + d] = su;
}

__global__ void reduce_final()
{
    int b = blockIdx.x;
    int i = threadIdx.x;
    float acc = 0.f;
    for (int c = 0; c < 16; c++)
        acc += g_Spart[((size_t)b * 16 + c) * 512 + i];
    g_S[(size_t)b * 512 + i] = acc;
}

// ---------------- band GEMM: tf32 mma -----------------------------------
#define MMA_TF32(d, a, b) \
    asm volatile("mma.sync.aligned.m16n8k8.row.col.f32.tf32.tf32.f32 " \
                 "{%0,%1,%2,%3},{%4,%5,%6,%7},{%8,%9},{%0,%1,%2,%3};" \
                 : "+f"(d[0]), "+f"(d[1]), "+f"(d[2]), "+f"(d[3]) \
                 : "r"(a[0]), "r"(a[1]), "r"(a[2]), "r"(a[3]), "r"(b[0]), "r"(b[1]))

#define SPA 44
#define SPB 136

__global__ void __launch_bounds__(256, 2) band_gemm()
{
    __shared__ float sA[128 * SPA];
    __shared__ float sB[32 * SPB];

    const int tid = threadIdx.x;
    const int n0 = blockIdx.x * 128;
    const int t0 = blockIdx.y * 128;
    const int b  = blockIdx.z;

    const float* Ag = g_cwA + (size_t)t0 * KBAND;
    const float* Bg = g_uek + (size_t)b * PADT * 512;

    const int alrow = tid >> 1;
    const int akseg = (tid & 1) * 16;
    const int bkrow = tid >> 3;
    const int bcseg = (tid & 7) * 16;

    const int lane = tid & 31, w = tid >> 5;
    const int wm = w & 1, wn = w >> 1;
    const int quad = lane >> 2, qt = lane & 3;

    float acc[4][4][4];
#pragma unroll
    for (int i = 0; i < 4; i++)
#pragma unroll
        for (int j = 0; j < 4; j++)
#pragma unroll
            for (int e = 0; e < 4; e++) acc[i][j][e] = 0.f;

    for (int k0 = 0; k0 < KBAND; k0 += 32) {
        const float* ap = Ag + (size_t)alrow * KBAND + k0 + akseg;
        const float* bp = Bg + (size_t)(t0 + 1 + k0 + bkrow) * 512 + n0 + bcseg;
        float* sa = &sA[alrow * SPA + akseg];
        float* sb = &sB[bkrow * SPB + bcseg];
#pragma unroll
        for (int cc = 0; cc < 4; cc++) *(float4*)(sa + cc * 4) = *(const float4*)(ap + cc * 4);
#pragma unroll
        for (int cc = 0; cc < 4; cc++) *(float4*)(sb + cc * 4) = *(const float4*)(bp + cc * 4);
        __syncthreads();

#pragma unroll
        for (int kk = 0; kk < 32; kk += 8) {
            uint32_t afr[4][4], bfr[4][2];
#pragma unroll
            for (int i = 0; i < 4; i++) {
                int m = wm * 64 + i * 16 + quad;
                afr[i][0] = *(const uint32_t*)&sA[m * SPA + kk + qt];
                afr[i][1] = *(const uint32_t*)&sA[(m + 8) * SPA + kk + qt];
                afr[i][2] = *(const uint32_t*)&sA[m * SPA + kk + qt + 4];
                afr[i][3] = *(const uint32_t*)&sA[(m + 8) * SPA + kk + qt + 4];
            }
#pragma unroll
            for (int j = 0; j < 4; j++) {
                int n = wn * 32 + j * 8 + quad;
                bfr[j][0] = *(const uint32_t*)&sB[(kk + qt) * SPB + n];
                bfr[j][1] = *(const uint32_t*)&sB[(kk + qt + 4) * SPB + n];
            }
#pragma unroll
            for (int i = 0; i < 4; i++)
#pragma unroll
                for (int j = 0; j < 4; j++) MMA_TF32(acc[i][j], afr[i], bfr[j]);
        }
        __syncthreads();
    }

    float* C = g_nd + (size_t)(b * TT + t0) * 512;
#pragma unroll
    for (int i = 0; i < 4; i++) {
#pragma unroll
        for (int j = 0; j < 4; j++) {
            int r = wm * 64 + i * 16 + quad;
            int cc = n0 + wn * 32 + j * 8 + qt * 2;
            *(float2*)&C[(size_t)r * 512 + cc] = make_float2(acc[i][j][0], acc[i][j][1]);
            *(float2*)&C[(size_t)(r + 8) * 512 + cc] = make_float2(acc[i][j][2], acc[i][j][3]);
        }
    }
}

// ---------------- final gating + split for output GEMM ----------------------
__global__ void ybuild()
{
    int r = blockIdx.x;
    int b = r >> 11;
    int d = threadIdx.x;
    float sq  = g_qkv[(size_t)r * QKV_LD + d];
    float num = g_S[(size_t)b * 512 + 256 + d] + g_nd[(size_t)r * 512 + d];
    float den = g_S[(size_t)b * 512 + d]       + g_nd[(size_t)r * 512 + 256 + d];
    float y = sq * num / den;
    __nv_bfloat16 h, l; split1(y, h, l);
    g_yh[(size_t)r * 256 + d] = h;
    g_yl[(size_t)r * 256 + d] = l;
}

// ---------------- launch ----------------------------------------------------
extern "C" void kernel_launch(void* const* d_in, const int* in_sizes, int n_in,
                              void* d_out, int out_size)
{
    const float* x      = (const float*)d_in[0];
    const float* Wq     = (const float*)d_in[1];
    const float* Wk     = (const float*)d_in[2];
    const float* Wv     = (const float*)d_in[3];
    const float* Wo     = (const float*)d_in[4];
    const float* w_bias = (const float*)d_in[5];
    float* out = (float*)d_out;

    float* qkv = nullptr;
    cudaGetSymbolAddress((void**)&qkv, g_qkv);
    __nv_bfloat16 *xh, *xl, *yh, *yl, *wqh, *wql, *woh, *wol;
    cudaGetSymbolAddress((void**)&xh, g_xh);
    cudaGetSymbolAddress((void**)&xl, g_xl);
    cudaGetSymbolAddress((void**)&yh, g_yh);
    cudaGetSymbolAddress((void**)&yl, g_yl);
    cudaGetSymbolAddress((void**)&wqh, g_wqkvTh);
    cudaGetSymbolAddress((void**)&wql, g_wqkvTl);
    cudaGetSymbolAddress((void**)&woh, g_woTh);
    cudaGetSymbolAddress((void**)&wol, g_woTl);

    // No static guards: set the attribute unconditionally (idempotent, cheap).
    cudaFuncSetAttribute(gemm_bf16x3,
                         cudaFuncAttributeMaxDynamicSharedMemorySize, GSMEM_BYTES);

    // splits + band coefficient matrix + pad zeroing (independent prep)
    split_x<<<(BT * 256) / (256 * 4), 256>>>(x);
    split_wT<<<1024, 256>>>(Wq, Wk, Wv, Wo);
    build_cwA<<<TT, KBAND>>>(w_bias);
    zero_uek_pad<<<(BB * 384 * 512) / (256 * 4), 256>>>();

    // fused QKV projection: [32768,256] x [256,768] -> packed q|k|v
    gemm_bf16x3<<<dim3(768 / 128, BT / 128), 256, GSMEM_BYTES>>>(xh, xl, wqh, wql, qkv, QKV_LD);

    // elementwise + uek materialization + global sums
    ew_reduce<<<dim3(16, BB), 256>>>();
    reduce_final<<<BB, 512>>>();

    // banded num/den corrections via tf32 tensor cores
    band_gemm<<<dim3(4, 16, BB), 256>>>();

    // gating + split, then output projection
    ybuild<<<BT, 256>>>();
    gemm_bf16x3<<<dim3(256 / 128, BT / 128), 256, GSMEM_BYTES>>>(yh, yl, woh, wol, out, DD);
}